// round 2
// baseline (speedup 1.0000x reference)
#include <cuda_runtime.h>

#define BB 4
#define NN 2048
#define INF 256
#define HH 8
#define DD 32
#define ALPHA 0.2f

// scratch (allocation-free rule: __device__ globals)
__device__ float g_Wh[BB*HH*NN*DD];   // [b][h][n][d]
__device__ float g_es[BB*HH*NN];      // e_i
__device__ float g_ed[BB*HH*NN];      // e_j

// ---------------------------------------------------------------------------
// Kernel 1: Wh = x @ W per head, plus e_src = Wh·a[:D], e_dst = Wh·a[D:]
// grid (B*N/64, H), 256 threads. smem: x tile 64x256 (64KB) + W 256x32 (32KB)
// ---------------------------------------------------------------------------
__global__ __launch_bounds__(256) void k1_proj(const float* __restrict__ x,
                                               const float* __restrict__ W,
                                               const float* __restrict__ a) {
    extern __shared__ float sm[];
    float* xs = sm;                // [64][256]
    float* Ws = sm + 64 * INF;     // [256][32]
    const int h  = blockIdx.y;
    const int b  = blockIdx.x >> 5;
    const int n0 = (blockIdx.x & 31) * 64;
    const int t  = threadIdx.x;

    // load x tile: 16384 floats = 4096 float4
    const float4* xg = (const float4*)(x + ((size_t)b * NN + n0) * INF);
    float4* xs4 = (float4*)xs;
#pragma unroll
    for (int l = 0; l < 16; l++) xs4[t + l * 256] = xg[t + l * 256];
    // load W[h]: 8192 floats = 2048 float4
    const float4* wg = (const float4*)(W + (size_t)h * INF * DD);
    float4* ws4 = (float4*)Ws;
#pragma unroll
    for (int l = 0; l < 8; l++) ws4[t + l * 256] = wg[t + l * 256];
    __syncthreads();

    const int d = t & 31;
    const int g = t >> 5;          // warp id: rows g*8..g*8+7
    float acc[8];
#pragma unroll
    for (int r = 0; r < 8; r++) acc[r] = 0.f;

    for (int kq = 0; kq < INF / 4; kq++) {
        const float w0 = Ws[(kq * 4 + 0) * DD + d];
        const float w1 = Ws[(kq * 4 + 1) * DD + d];
        const float w2 = Ws[(kq * 4 + 2) * DD + d];
        const float w3 = Ws[(kq * 4 + 3) * DD + d];
#pragma unroll
        for (int r = 0; r < 8; r++) {
            const float4 xv = *(const float4*)&xs[(g * 8 + r) * INF + kq * 4];
            acc[r] = fmaf(xv.x, w0, fmaf(xv.y, w1, fmaf(xv.z, w2, fmaf(xv.w, w3, acc[r]))));
        }
    }

    const float asrc = a[h * 2 * DD + d];
    const float adst = a[h * 2 * DD + DD + d];
#pragma unroll
    for (int r = 0; r < 8; r++) {
        const int n = n0 + g * 8 + r;
        g_Wh[(((size_t)b * HH + h) * NN + n) * DD + d] = acc[r];
        float es = acc[r] * asrc;
        float ed = acc[r] * adst;
#pragma unroll
        for (int off = 16; off; off >>= 1) {
            es += __shfl_xor_sync(0xffffffffu, es, off);
            ed += __shfl_xor_sync(0xffffffffu, ed, off);
        }
        if (d == 0) {
            g_es[((size_t)b * HH + h) * NN + n] = es;
            g_ed[((size_t)b * HH + h) * NN + n] = ed;
        }
    }
}

// ---------------------------------------------------------------------------
// Kernel 2: flash-style masked softmax + PV, all 8 heads per block.
// grid B*(N/32) = 256 blocks, 256 threads. 32-wide j tiles.
//   phase A identity: thread t = pair (i = t/8, h = t%8); denom lives in reg.
//   phase B identity: lane d = t%32, warp w = t/32 owns i in [4w,4w+4) x all h.
// smem: p[32j][256pair] 32KB | Wh[8h][32j][32d] 32KB | adj 4KB | ed 1KB | den 1KB
// ---------------------------------------------------------------------------
__global__ __launch_bounds__(256) void k2_attn(const int* __restrict__ adj,
                                               float* __restrict__ out) {
    extern __shared__ float sm[];
    float* p_s   = sm;                      // [j][pair] : 8192
    float* wh_s  = sm + 8192;               // [h][j][d] : 8192
    int*   adjs  = (int*)(sm + 16384);      // [i][j]    : 1024
    float* ed_s  = sm + 16384 + 1024;       // [j][h]    : 256
    float* den_s = ed_s + 256;              // [pair]    : 256

    const int b  = blockIdx.x >> 6;
    const int i0 = (blockIdx.x & 63) * 32;
    const int t  = threadIdx.x;
    const int ai = t >> 3, ah = t & 7;      // phase A pair
    const int d  = t & 31, w = t >> 5;      // phase B identity

    const float ei = g_es[((size_t)b * HH + ah) * NN + i0 + ai];
    float denom = 0.f;
    float acc[4][8];
#pragma unroll
    for (int i = 0; i < 4; i++)
#pragma unroll
        for (int h = 0; h < 8; h++) acc[i][h] = 0.f;

    const int lh = t >> 5, lj = t & 31;     // ed loader identity

    for (int jt = 0; jt < NN / 32; jt++) {
        const int j0 = jt * 32;
        // --- loads ---
        {   // adj tile: row = t>>3 (0..31), int4 col = t&7
            const int row = t >> 3, c = t & 7;
            const int4* ag = (const int4*)(adj + ((size_t)b * NN + i0 + row) * NN + j0);
            ((int4*)adjs)[row * 8 + c] = ag[c];
        }
        {   // Wh tile: 2048 float4
#pragma unroll
            for (int l = 0; l < 8; l++) {
                const int idx = t + l * 256;          // [h][j][d4]
                const int hh = idx >> 8;
                const int jj = (idx >> 3) & 31;
                const int d4 = idx & 7;
                ((float4*)wh_s)[idx] =
                    ((const float4*)g_Wh)[(((size_t)b * HH + hh) * NN + j0 + jj) * 8 + d4];
            }
        }
        // ed tile transposed [j][h]
        ed_s[lj * 8 + lh] = g_ed[((size_t)b * HH + lh) * NN + j0 + lj];
        __syncthreads();

        // --- phase A: p = adj ? exp(leaky(ei+ej)) : 0 (no max pass: |s| <~ 12) ---
        const int* arow = adjs + ai * 32;
#pragma unroll
        for (int j = 0; j < 32; j++) {
            float s = ei + ed_s[j * 8 + ah];
            s = fmaxf(s, ALPHA * s);
            const float pv = arow[j] ? __expf(s) : 0.f;
            denom += pv;
            p_s[j * 256 + t] = pv;
        }
        __syncthreads();

        // --- phase B: rank-32 update, FFMA-bound ---
#pragma unroll 2
        for (int j = 0; j < 32; j++) {
            float wh[8];
#pragma unroll
            for (int h = 0; h < 8; h++) wh[h] = wh_s[h * 1024 + j * 32 + d];
#pragma unroll
            for (int i = 0; i < 4; i++) {
                const float4 p0 = *(const float4*)&p_s[j * 256 + (w * 4 + i) * 8];
                const float4 p1 = *(const float4*)&p_s[j * 256 + (w * 4 + i) * 8 + 4];
                acc[i][0] = fmaf(p0.x, wh[0], acc[i][0]);
                acc[i][1] = fmaf(p0.y, wh[1], acc[i][1]);
                acc[i][2] = fmaf(p0.z, wh[2], acc[i][2]);
                acc[i][3] = fmaf(p0.w, wh[3], acc[i][3]);
                acc[i][4] = fmaf(p1.x, wh[4], acc[i][4]);
                acc[i][5] = fmaf(p1.y, wh[5], acc[i][5]);
                acc[i][6] = fmaf(p1.z, wh[6], acc[i][6]);
                acc[i][7] = fmaf(p1.w, wh[7], acc[i][7]);
            }
        }
        __syncthreads();  // protect smem before next tile's loads
    }

    den_s[t] = denom;
    __syncthreads();

#pragma unroll
    for (int i = 0; i < 4; i++) {
        const int row = i0 + w * 4 + i;
#pragma unroll
        for (int h = 0; h < 8; h++) {
            const float rd = 1.f / den_s[(w * 4 + i) * 8 + h];
            out[(((size_t)b * NN) + row) * (HH * DD) + h * DD + d] = acc[i][h] * rd;
        }
    }
}

extern "C" void kernel_launch(void* const* d_in, const int* in_sizes, int n_in,
                              void* d_out, int out_size) {
    const float* x   = (const float*)d_in[0];
    const int*   adj = (const int*)d_in[1];
    const float* W   = (const float*)d_in[2];
    const float* a   = (const float*)d_in[3];
    float* out = (float*)d_out;

    // idempotent, called every launch (no static guards)
    cudaFuncSetAttribute(k1_proj, cudaFuncAttributeMaxDynamicSharedMemorySize, 98304);
    cudaFuncSetAttribute(k2_attn, cudaFuncAttributeMaxDynamicSharedMemorySize, 71680);

    k1_proj<<<dim3(128, 8), 256, 98304>>>(x, W, a);
    k2_attn<<<256, 256, 71680>>>(adj, out);
}